// round 5
// baseline (speedup 1.0000x reference)
#include <cuda_runtime.h>
#include <cstdint>

// Problem dimensions (fixed by the dataset)
#define BB 16
#define NN 32768
#define CC 128
#define SS 1024

// FPS kernel tiling
#define GG 8                 // CTAs per batch == cluster size (portable max)
#define TT 256               // threads per CTA
#define CHUNK (NN / GG)      // 4096 points per CTA
#define KK (CHUNK / TT)      // 16 points per thread (live in registers)

// Scratch (allocation-free rule: __device__ globals)
__device__ float g_px[BB * NN];
__device__ float g_py[BB * NN];
__device__ float g_pz[BB * NN];
__device__ int   g_idx[BB * SS];

// ---------------------------------------------------------------------------
// Key packing: for non-negative floats the IEEE754 bit pattern is monotone,
// so key = (bits(v) << 32) | (0xFFFFFFFF - idx) makes unsigned 64-bit max
// equivalent to "max v, ties -> lowest idx" (JAX argmax = first max).
// Distances are always >= 0 (squares, min with FLT_MAX), so this is exact.
// ---------------------------------------------------------------------------
__device__ __forceinline__ uint64_t pack_key(float v, int idx) {
    return ((uint64_t)__float_as_uint(v) << 32) |
           (uint64_t)(0xFFFFFFFFu - (uint32_t)idx);
}
__device__ __forceinline__ int key_idx(uint64_t k) {
    return (int)(0xFFFFFFFFu - (uint32_t)k);
}

// ---------------------------------------------------------------------------
// Prep: transpose p [B, N, 3] (AoS) -> SoA px/py/pz for coalesced loads.
// ---------------------------------------------------------------------------
__global__ void prep_kernel(const float* __restrict__ p) {
    int i = blockIdx.x * blockDim.x + threadIdx.x;
    if (i < BB * NN) {
        const float* s = p + 3 * (size_t)i;
        g_px[i] = __ldg(s + 0);
        g_py[i] = __ldg(s + 1);
        g_pz[i] = __ldg(s + 2);
    }
}

// ---------------------------------------------------------------------------
// Cluster helpers
// ---------------------------------------------------------------------------
__device__ __forceinline__ uint32_t mapa_u32(uint32_t addr, uint32_t rank) {
    uint32_t r;
    asm("mapa.shared::cluster.u32 %0, %1, %2;" : "=r"(r) : "r"(addr), "r"(rank));
    return r;
}

__device__ __forceinline__ void st_cluster_v4(uint32_t addr, float a, float b,
                                              float c, float d) {
    asm volatile("st.shared::cluster.v4.f32 [%0], {%1, %2, %3, %4};"
                 :: "r"(addr), "f"(a), "f"(b), "f"(c), "f"(d) : "memory");
}

// Cluster record: {key_lo, key_hi, x, y} in v4 slot, z at +16. 32-byte stride
// per rank -> 8 ranks span 256 B; broadcast LDS reads are conflict-free.
struct __align__(32) Rec {
    float4 a;   // {key_lo, key_hi, x, y}
    float  z;
    float  pad[3];
};

// ---------------------------------------------------------------------------
// Main FPS kernel: one cluster of GG CTAs per batch. Points live in registers.
// Per iteration:
//   phase1: register distance update + min + thread-local argmax (packed key)
//   warp shuffle reduce of {key, x, y, z} (64-bit max key = first-max argmax)
//   cross-warp reduce in smem; CTA record pushed to all peers via DSMEM
//   one cluster barrier; every thread reduces the GG records -> next q.
// No global memory traffic on the critical path (one STG of the index/step).
// ---------------------------------------------------------------------------
__global__ void __cluster_dims__(GG, 1, 1) __launch_bounds__(TT, 1)
fps_kernel() {
    const int b    = blockIdx.x / GG;   // batch
    const int r    = blockIdx.x % GG;   // cluster rank (chunk)
    const int t    = threadIdx.x;
    const int w    = t >> 5;
    const int lane = t & 31;

    __shared__ uint64_t wk_s[TT / 32];
    __shared__ float    wx_s[TT / 32], wy_s[TT / 32], wz_s[TT / 32];
    // Double-buffered cluster records (written remotely via DSMEM).
    __shared__ Rec rec[2][GG];

    // Load this thread's 16 points into registers (coalesced from SoA).
    float X[KK], Y[KK], Z[KK], MD[KK];
    const int base = b * NN + r * CHUNK;
#pragma unroll
    for (int k = 0; k < KK; k++) {
        int li = k * TT + t;
        X[k]  = g_px[base + li];
        Y[k]  = g_py[base + li];
        Z[k]  = g_pz[base + li];
        MD[k] = 3.402823466e38f;   // finfo(float32).max, matches reference init
    }

    // Batch-local index of this thread's k-th point: idx0 + k*TT.
    const int idx0 = r * CHUNK + t;

    // First sample is index 0; q = p[b][0].
    float qx = g_px[b * NN], qy = g_py[b * NN], qz = g_pz[b * NN];
    if (r == 0 && t == 0) g_idx[b * SS] = 0;

    for (int i = 1; i < SS; i++) {
        // ---- Phase 1: distance update + thread-local argmax (registers only)
        float bv = -1.0f;
        int   bk = 0;
#pragma unroll
        for (int k = 0; k < KK; k++) {
            // Reference op order, no FMA contraction: d = ((dx*dx + dy*dy) + dz*dz)
            float dx = __fsub_rn(X[k], qx);
            float dy = __fsub_rn(Y[k], qy);
            float dz = __fsub_rn(Z[k], qz);
            float d  = __fadd_rn(__fadd_rn(__fmul_rn(dx, dx), __fmul_rn(dy, dy)),
                                 __fmul_rn(dz, dz));
            float m  = fminf(MD[k], d);
            MD[k]    = m;
            // Strict '>' keeps the lowest index on ties (k ascending => idx ascending)
            if (m > bv) { bv = m; bk = k; }
        }
        // Recover winner coords with an unrolled select chain (avoids dynamic
        // register indexing / local-memory spill).
        float bx = X[0], by = Y[0], bz = Z[0];
#pragma unroll
        for (int k = 1; k < KK; k++) {
            if (bk == k) { bx = X[k]; by = Y[k]; bz = Z[k]; }
        }
        uint64_t key = pack_key(bv, idx0 + bk * TT);

        // ---- Warp reduce: 64-bit max key (carries argmax + tie-break) + coords.
#pragma unroll
        for (int s = 16; s > 0; s >>= 1) {
            uint64_t ok = __shfl_down_sync(0xffffffffu, key, s);
            float    ox = __shfl_down_sync(0xffffffffu, bx, s);
            float    oy = __shfl_down_sync(0xffffffffu, by, s);
            float    oz = __shfl_down_sync(0xffffffffu, bz, s);
            if (ok > key) { key = ok; bx = ox; by = oy; bz = oz; }
        }
        if (lane == 0) {
            wk_s[w] = key; wx_s[w] = bx; wy_s[w] = by; wz_s[w] = bz;
        }
        __syncthreads();

        const int par = i & 1;
        // ---- Threads 0..GG-1 each redundantly reduce the 8 warp records
        //      (broadcast LDS, conflict-free) and push the CTA record to peer
        //      CTA `t`'s slot [par][r] via DSMEM.
        if (t < GG) {
            uint64_t kk2 = wk_s[0];
            float xx = wx_s[0], yy = wy_s[0], zz = wz_s[0];
#pragma unroll
            for (int j = 1; j < TT / 32; j++) {
                uint64_t k2 = wk_s[j];
                if (k2 > kk2) { kk2 = k2; xx = wx_s[j]; yy = wy_s[j]; zz = wz_s[j]; }
            }
            uint32_t local0 = (uint32_t)__cvta_generic_to_shared(&rec[par][r]);
            uint32_t rem    = mapa_u32(local0, (uint32_t)t);
            st_cluster_v4(rem, __uint_as_float((uint32_t)kk2),
                               __uint_as_float((uint32_t)(kk2 >> 32)), xx, yy);
            asm volatile("st.shared::cluster.f32 [%0], %1;"
                         :: "r"(rem + 16), "f"(zz) : "memory");
        }

        // One cluster barrier per step: release/acquire orders the DSMEM
        // stores and doubles as the CTA-wide barrier. All threads execute it.
        asm volatile("barrier.cluster.arrive.aligned;" ::: "memory");
        asm volatile("barrier.cluster.wait.aligned;"   ::: "memory");

        // ---- Phase 2: every thread reduces the GG records locally -> winner.
        float4   a0  = rec[par][0].a;
        uint64_t wkk = ((uint64_t)__float_as_uint(a0.y) << 32) |
                       (uint64_t)__float_as_uint(a0.x);
        qx = a0.z; qy = a0.w; qz = rec[par][0].z;
#pragma unroll
        for (int j = 1; j < GG; j++) {
            float4   a2 = rec[par][j].a;
            uint64_t k2 = ((uint64_t)__float_as_uint(a2.y) << 32) |
                          (uint64_t)__float_as_uint(a2.x);
            if (k2 > wkk) { wkk = k2; qx = a2.z; qy = a2.w; qz = rec[par][j].z; }
        }
        if (r == 0 && t == 0) g_idx[b * SS + i] = key_idx(wkk);
    }
}

// ---------------------------------------------------------------------------
// Fused gather: thread ids [0, B*S) copy p_out [B, S, 3];
//               thread ids [B*S, B*S + B*C*S) gather x_out [B, C, S].
// d_out layout: p_out (B*S*3 floats) followed by x_out (B*C*S floats).
// ---------------------------------------------------------------------------
__global__ void gather_kernel(const float* __restrict__ p,
                              const float* __restrict__ x,
                              float* __restrict__ out) {
    int tid = blockIdx.x * blockDim.x + threadIdx.x;
    if (tid < BB * SS) {
        // p_out
        int b   = tid / SS;
        int idx = g_idx[tid];
        const float* src = p + ((size_t)b * NN + idx) * 3;
        float* dst = out + (size_t)tid * 3;
        float v0 = __ldg(src + 0);
        float v1 = __ldg(src + 1);
        float v2 = __ldg(src + 2);
        dst[0] = v0; dst[1] = v1; dst[2] = v2;
    } else if (tid < BB * SS + BB * CC * SS) {
        // x_out
        int e  = tid - BB * SS;         // < B*C*S = 2M
        int s  = e % SS;
        int bc = e / SS;                // b*C + c
        int b  = bc / CC;
        int idx = g_idx[b * SS + s];
        out[BB * SS * 3 + e] = __ldg(x + (size_t)bc * NN + idx);
    }
}

// ---------------------------------------------------------------------------
// Launch: prep -> FPS (persistent cluster kernel) -> fused gather.
// All plain kernel launches; graph-capturable, allocation-free.
// ---------------------------------------------------------------------------
extern "C" void kernel_launch(void* const* d_in, const int* in_sizes, int n_in,
                              void* d_out, int out_size) {
    const float* p = (const float*)d_in[0];   // [B, N, 3]
    const float* x = (const float*)d_in[1];   // [B, C, N]
    float* out = (float*)d_out;

    prep_kernel<<<(BB * NN + 255) / 256, 256>>>(p);
    fps_kernel<<<BB * GG, TT>>>();
    const int gtotal = BB * SS + BB * CC * SS;
    gather_kernel<<<(gtotal + 255) / 256, 256>>>(p, x, out);
}